// round 13
// baseline (speedup 1.0000x reference)
#include <cuda_runtime.h>
#include <cuda_bf16.h>
#include <cstdint>

// Problem constants
#define BB 64
#define SS 512
#define EE 768
#define HH 256
#define G4 1024    // 4*H
#define MM (BB*SS) // 32768 rows

// ---------------- scratch (device globals; no allocation allowed) ----------------
__device__ float g_xzf[MM * G4];        // x @ kernel_f + bias_f
__device__ float g_xzb[MM * G4];        // x @ kernel_b + bias_b
__device__ float g_hf[MM * HH];         // forward h history
__device__ float g_hb[MM * HH];         // backward h history (un-reversed)

// per-(dir, batch-group) h exchange ping-pong (bf16 hi/lo): [dir][bg][par][16*256]
__device__ __nv_bfloat16 g_hxh[2][4][2][16 * HH];
__device__ __nv_bfloat16 g_hxl[2][4][2][16 * HH];
__device__ unsigned g_flag[2][4][16];   // per-(dir,bg,cg) step flags

// bf16 split operands for input GEMM
__device__ __nv_bfloat16 g_xh[MM * EE];           // hi(x)
__device__ __nv_bfloat16 g_xl[MM * EE];           // lo(x)
__device__ __nv_bfloat16 g_wt[2][2][G4 * EE];     // [dir][hi/lo] W^T as [n][k]

// rec^T bf16 hi/lo: [dir][hi/lo][col(1024)][k(256)]
__device__ __nv_bfloat16 g_recT[2][2][G4 * HH];

// ---------------- PTX helpers ----------------
__device__ __forceinline__ uint32_t smem_u32(const void* p) {
    uint32_t a;
    asm("{ .reg .u64 t; cvta.to.shared.u64 t, %1; cvt.u32.u64 %0, t; }" : "=r"(a) : "l"(p));
    return a;
}
__device__ __forceinline__ void cp16(uint32_t s, const void* g) {
    asm volatile("cp.async.cg.shared.global [%0], [%1], 16;" :: "r"(s), "l"(g));
}
#define CP_COMMIT() asm volatile("cp.async.commit_group;" ::: "memory")
#define CP_WAIT0()  asm volatile("cp.async.wait_group 0;" ::: "memory")
#define CP_WAIT1()  asm volatile("cp.async.wait_group 1;" ::: "memory")

#define LDSM4(R, addr) \
    asm volatile("ldmatrix.sync.aligned.m8n8.x4.shared.b16 {%0,%1,%2,%3}, [%4];" \
        : "=r"((R)[0]), "=r"((R)[1]), "=r"((R)[2]), "=r"((R)[3]) : "r"(addr))

#define LDSM2(R, addr) \
    asm volatile("ldmatrix.sync.aligned.m8n8.x2.shared.b16 {%0,%1}, [%2];" \
        : "=r"((R)[0]), "=r"((R)[1]) : "r"(addr))

#define MMA16816(d, a, b) \
    asm volatile("mma.sync.aligned.m16n8k16.row.col.f32.bf16.bf16.f32 " \
        "{%0,%1,%2,%3}, {%4,%5,%6,%7}, {%8,%9}, {%0,%1,%2,%3};" \
        : "+f"((d)[0]), "+f"((d)[1]), "+f"((d)[2]), "+f"((d)[3]) \
        : "r"((a)[0]), "r"((a)[1]), "r"((a)[2]), "r"((a)[3]), "r"((b)[0]), "r"((b)[1]))

__device__ __forceinline__ void st16cg(void* p, unsigned short v) {
    asm volatile("st.global.cg.u16 [%0], %1;" :: "l"(p), "h"(v));
}

// ---------------- init: zero flags + h exchange buffers ----------------
__global__ void init_k() {
    int i = blockIdx.x * blockDim.x + threadIdx.x;
    if (i < 2 * 4 * 16) (&g_flag[0][0][0])[i] = 0u;
    int stride = gridDim.x * blockDim.x;
    __nv_bfloat16 z = __float2bfloat16(0.f);
    for (int k = i; k < 2 * 4 * 2 * 16 * HH; k += stride) {
        (&g_hxh[0][0][0][0])[k] = z;
        (&g_hxl[0][0][0][0])[k] = z;
    }
}

// ---------------- prep: bf16 hi/lo splits ----------------
__global__ __launch_bounds__(256) void split_x(const float* __restrict__ x) {
    int stride = gridDim.x * blockDim.x;
    const int n4 = MM * EE / 4;
    for (int i = blockIdx.x * blockDim.x + threadIdx.x; i < n4; i += stride) {
        float4 v = *(const float4*)(x + i * 4);
        __nv_bfloat16 h0 = __float2bfloat16(v.x), h1 = __float2bfloat16(v.y);
        __nv_bfloat16 h2 = __float2bfloat16(v.z), h3 = __float2bfloat16(v.w);
        __nv_bfloat162* dh = (__nv_bfloat162*)(g_xh + i * 4);
        __nv_bfloat162* dl = (__nv_bfloat162*)(g_xl + i * 4);
        dh[0] = __nv_bfloat162(h0, h1);
        dh[1] = __nv_bfloat162(h2, h3);
        dl[0] = __nv_bfloat162(__float2bfloat16(v.x - __bfloat162float(h0)),
                               __float2bfloat16(v.y - __bfloat162float(h1)));
        dl[1] = __nv_bfloat162(__float2bfloat16(v.z - __bfloat162float(h2)),
                               __float2bfloat16(v.w - __bfloat162float(h3)));
    }
}
__global__ __launch_bounds__(256) void split_w(const float* __restrict__ kf,
                                               const float* __restrict__ kb) {
    int stride = gridDim.x * blockDim.x;
    for (int i = blockIdx.x * blockDim.x + threadIdx.x; i < EE * G4; i += stride) {
        int n = i & (G4 - 1), k = i >> 10;
        float vf = kf[i], vb = kb[i];
        __nv_bfloat16 hf16 = __float2bfloat16(vf);
        __nv_bfloat16 hb16 = __float2bfloat16(vb);
        g_wt[0][0][n * EE + k] = hf16;
        g_wt[0][1][n * EE + k] = __float2bfloat16(vf - __bfloat162float(hf16));
        g_wt[1][0][n * EE + k] = hb16;
        g_wt[1][1][n * EE + k] = __float2bfloat16(vb - __bfloat162float(hb16));
    }
}
__global__ __launch_bounds__(256) void split_rec(const float* __restrict__ rf,
                                                 const float* __restrict__ rb) {
    int stride = gridDim.x * blockDim.x;
    for (int i = blockIdx.x * blockDim.x + threadIdx.x; i < HH * G4; i += stride) {
        int k = i >> 10, col = i & (G4 - 1);
        float vf = rf[i], vb = rb[i];
        __nv_bfloat16 hf16 = __float2bfloat16(vf);
        __nv_bfloat16 hb16 = __float2bfloat16(vb);
        g_recT[0][0][col * HH + k] = hf16;
        g_recT[0][1][col * HH + k] = __float2bfloat16(vf - __bfloat162float(hf16));
        g_recT[1][0][col * HH + k] = hb16;
        g_recT[1][1][col * HH + k] = __float2bfloat16(vb - __bfloat162float(hb16));
    }
}

// ---------------- phase 1: mma.sync bf16 GEMM  xz = x @ W + bias ----------------
// R11 shape (proven ~930us): 3-term split over K' = 3*768: chunks [0,12)=Ah*Bh,
// [12,24)=Al*Bh, [24,36)=Ah*Bl. CTA tile 128x128, BK=64, 256 thr, 2-stage cp.async.
#define NKCH 36
#define GPAD 72
#define GEMM_SMEM (2 * 2 * 128 * GPAD * 2)   // 147456 B dynamic

__global__ __launch_bounds__(256) void gemm_mma(
    const float* __restrict__ bias_f, const float* __restrict__ bias_b)
{
    extern __shared__ __nv_bfloat16 gsm[];
    __nv_bfloat16* sA = gsm;                  // [2][128][GPAD]
    __nv_bfloat16* sB = gsm + 2 * 128 * GPAD; // [2][128][GPAD]

    const int t = threadIdx.x, lane = t & 31, w = t >> 5;
    const int dir = blockIdx.z;
    const int m0 = blockIdx.y * 128;
    const int n0 = blockIdx.x * 128;

    const __nv_bfloat16* wth = &g_wt[dir][0][0];
    const __nv_bfloat16* wtl = &g_wt[dir][1][0];
    const float* bias = dir ? bias_b : bias_f;
    float* out = dir ? g_xzb : g_xzf;

    const uint32_t sAu = smem_u32(sA);
    const uint32_t sBu = smem_u32(sB);

    float acc[2][8][4];
#pragma unroll
    for (int i = 0; i < 2; i++)
#pragma unroll
        for (int j = 0; j < 8; j++)
#pragma unroll
            for (int k = 0; k < 4; k++) acc[i][j][k] = 0.f;

    const int lrow = t >> 3, lcol8 = t & 7;

    const int wm = (w & 3) * 32, wn = (w >> 2) * 64;
    const int aRow = wm + (lane & 15);
    const int aCol = (lane >> 4) * 8;
    const int bRow = wn + (lane & 7) + ((lane & 16) ? 8 : 0);
    const int bCol = ((lane >> 3) & 1) * 8;

#define LOAD_CHUNK(kc, buf) do {                                                   \
    int p_ = (kc) / 12, kk_ = (kc) - p_ * 12;                                      \
    const __nv_bfloat16* Ag_ = (p_ == 1) ? g_xl : g_xh;                            \
    const __nv_bfloat16* Bg_ = (p_ == 2) ? wtl : wth;                              \
    _Pragma("unroll")                                                              \
    for (int i_ = 0; i_ < 4; i_++) {                                               \
        int row_ = lrow + 32 * i_;                                                 \
        cp16(sAu + (((buf) * 128 + row_) * GPAD + lcol8 * 8) * 2,                  \
             Ag_ + (size_t)(m0 + row_) * EE + kk_ * 64 + lcol8 * 8);               \
        cp16(sBu + (((buf) * 128 + row_) * GPAD + lcol8 * 8) * 2,                  \
             Bg_ + (size_t)(n0 + row_) * EE + kk_ * 64 + lcol8 * 8);               \
    }                                                                              \
} while (0)

    LOAD_CHUNK(0, 0);
    CP_COMMIT();

    for (int kc = 0; kc < NKCH; kc++) {
        const int buf = kc & 1;
        CP_WAIT0();
        __syncthreads();
        if (kc + 1 < NKCH) { LOAD_CHUNK(kc + 1, buf ^ 1); CP_COMMIT(); }

#pragma unroll
        for (int k16 = 0; k16 < 64; k16 += 16) {
            uint32_t a[2][4];
#pragma unroll
            for (int mt = 0; mt < 2; mt++)
                LDSM4(a[mt], sAu + ((buf * 128 + aRow + mt * 16) * GPAD + k16 + aCol) * 2);
            uint32_t b[8][2];
#pragma unroll
            for (int i = 0; i < 4; i++) {
                uint32_t r[4];
                LDSM4(r, sBu + ((buf * 128 + bRow + i * 16) * GPAD + k16 + bCol) * 2);
                b[2 * i][0] = r[0]; b[2 * i][1] = r[1];
                b[2 * i + 1][0] = r[2]; b[2 * i + 1][1] = r[3];
            }
#pragma unroll
            for (int mt = 0; mt < 2; mt++)
#pragma unroll
                for (int nt = 0; nt < 8; nt++)
                    MMA16816(acc[mt][nt], a[mt], b[nt]);
        }
        __syncthreads();
    }
#undef LOAD_CHUNK

#pragma unroll
    for (int nt = 0; nt < 8; nt++) {
        const int col = n0 + wn + nt * 8 + (lane & 3) * 2;
        const float b0 = __ldg(bias + col), b1 = __ldg(bias + col + 1);
#pragma unroll
        for (int mt = 0; mt < 2; mt++) {
            const int r0 = m0 + wm + mt * 16 + (lane >> 2);
            float2 v0 = make_float2(acc[mt][nt][0] + b0, acc[mt][nt][1] + b1);
            float2 v1 = make_float2(acc[mt][nt][2] + b0, acc[mt][nt][3] + b1);
            *(float2*)(out + (size_t)r0 * G4 + col) = v0;
            *(float2*)(out + (size_t)(r0 + 8) * G4 + col) = v1;
        }
    }
}

// ---------------- phase 2: persistent recurrence, batch-split HMMA ----------------
// Grid: 128 CTAs = 2 dirs x 4 batch-groups(16 batches) x 16 col-groups(16 h-cols).
// Sync domain = 16 CTAs sharing (dir,bg); flag-based barrier (no atomics).
#define RPAD 264
#define XQ 20
#define ZPAD 68
#define SREC_SZ  (2 * 64 * RPAD * 2)                 // 67584
#define SH_OFF   SREC_SZ
#define SH_SZ    (2 * 16 * RPAD * 2)                 // 16896
#define SXZ_OFF  (SH_OFF + SH_SZ)
#define SXZ_SZ   (2 * 4 * 16 * XQ * 4)               // 10240
#define ZB_OFF   (SXZ_OFF + SXZ_SZ)
#define ZB_SZ    (16 * ZPAD * 4)                     // 4352
#define LSTM_SMEM (ZB_OFF + ZB_SZ)                   // 99072

__global__ __launch_bounds__(256) void lstm_rec()
{
    extern __shared__ char smem[];
    __nv_bfloat16* sRec = (__nv_bfloat16*)(smem);            // [2][64][RPAD]
    __nv_bfloat16* sH   = (__nv_bfloat16*)(smem + SH_OFF);   // [2][16][RPAD]
    float*         sXZ  = (float*)(smem + SXZ_OFF);          // [2][4][16][XQ]
    float*         zbuf = (float*)(smem + ZB_OFF);           // [16][ZPAD]

    const int t = threadIdx.x, lane = t & 31, w = t >> 5;
    const int bx  = blockIdx.x;
    const int dir = bx >> 6;
    const int bg  = (bx >> 4) & 3;
    const int cg  = bx & 15;
    const int hc0 = cg * 16;

    const float* xz = dir ? g_xzb : g_xzf;
    float*     hist = dir ? g_hb  : g_hf;

    const uint32_t sRu  = smem_u32(sRec);
    const uint32_t sHu  = smem_u32(sH);
    const uint32_t sXZu = smem_u32(sXZ);

    // ---- load rec^T slice: sRec[p][lc][k], gate col = (lc&3)*256 + hc0 + (lc>>2)
    for (int seg = t; seg < 4096; seg += 256) {          // 2p x 64lc x 32segs
        int p = seg >> 11, rem = seg & 2047;
        int lc = rem >> 5, s = rem & 31;
        int col = (lc & 3) * HH + hc0 + (lc >> 2);
        uint4 v = *(const uint4*)(&g_recT[dir][p][0] + (size_t)col * HH + s * 8);
        *(uint4*)&sRec[(p * 64 + lc) * RPAD + s * 8] = v;
    }

    // ---- fragment addresses (warp w owns lc [w*8, w*8+8))
    const uint32_t aBaseH = sHu + (uint32_t)((lane & 15) * RPAD + (lane >> 4) * 8) * 2;
    const uint32_t aBaseL = aBaseH + 16 * RPAD * 2;
    const uint32_t bBaseH = sRu + (uint32_t)((w * 8 + (lane & 7)) * RPAD
                                             + ((lane >> 3) & 1) * 8) * 2;
    const uint32_t bBaseL = bBaseH + 64 * RPAD * 2;

    // gate-thread mapping: fb = t&15 (batch), jl = t>>4 (one h-col each)
    const int fb = t & 15, jl = t >> 4;
    float cst = 0.f;

    // ---- xz prefetch: 256 16B segs, 1/thread: q = t>>6, b = (t>>2)&15, sg = t&3
    const int pq = t >> 6, pfb = (t >> 2) & 15, psg = t & 3;

#define XZ_PREFETCH(spos, buf) \
    cp16(sXZu + ((((buf) * 4 + pq) * 16 + pfb) * XQ + psg * 4) * 4, \
         xz + ((size_t)(bg * 16 + pfb) * SS + (spos)) * G4 + pq * HH + hc0 + psg * 4)

    {
        int spos0 = dir ? (SS - 1) : 0;
        XZ_PREFETCH(spos0, 0);
        CP_COMMIT();
    }
    __syncthreads();

    for (int step = 0; step < SS; step++) {
        const int par = step & 1;

        // ---- load h (hi/lo) into sH: 2p x 16rows x 32segs = 1024 segs
        const __nv_bfloat16* srcH = &g_hxh[dir][bg][par][0];
        const __nv_bfloat16* srcL = &g_hxl[dir][bg][par][0];
#pragma unroll
        for (int i = 0; i < 4; i++) {
            int seg = t + 256 * i;
            int p = seg >> 9, rem = seg & 511;
            int row = rem >> 5, s = rem & 31;
            uint4 v = __ldcg((const uint4*)((p ? srcL : srcH) + row * HH + s * 8));
            *(uint4*)&sH[(p * 16 + row) * RPAD + s * 8] = v;
        }

        // ---- prefetch xz for next step
        if (step + 1 < SS) {
            int spos1 = dir ? (SS - 2 - step) : (step + 1);
            XZ_PREFETCH(spos1, (step + 1) & 1);
            CP_COMMIT();
        }
        __syncthreads();

        // ---- z = h @ recT (3-term bf16 split), warp tile M16 x N8
        float aHH[4], aLH[4], aHL[4];
#pragma unroll
        for (int k = 0; k < 4; k++) { aHH[k] = 0.f; aLH[k] = 0.f; aHL[k] = 0.f; }

#pragma unroll
        for (int k16 = 0; k16 < 256; k16 += 16) {
            const uint32_t ko = (uint32_t)k16 * 2;
            uint32_t ah[4], al[4], bh[2], bl[2];
            LDSM4(ah, aBaseH + ko);
            LDSM4(al, aBaseL + ko);
            LDSM2(bh, bBaseH + ko);
            LDSM2(bl, bBaseL + ko);
            MMA16816(aHH, ah, bh);
            MMA16816(aLH, al, bh);
            MMA16816(aHL, ah, bl);
        }

        // ---- stage z to smem (sum split terms)
        {
            const int col = w * 8 + (lane & 3) * 2;
            const int row = lane >> 2;
            float z0 = aHH[0] + aLH[0] + aHL[0];
            float z1 = aHH[1] + aLH[1] + aHL[1];
            float z2 = aHH[2] + aLH[2] + aHL[2];
            float z3 = aHH[3] + aLH[3] + aHL[3];
            *(float2*)&zbuf[row * ZPAD + col] = make_float2(z0, z1);
            *(float2*)&zbuf[(row + 8) * ZPAD + col] = make_float2(z2, z3);
        }
        if (step + 1 < SS) { CP_WAIT1(); } else { CP_WAIT0(); }
        __syncthreads();

        // ---- gates, state update, publish h (one h-col per thread)
        {
            const int spos = dir ? (SS - 1 - step) : step;
            const int nxt = par ^ 1;
            float4 z4 = *(const float4*)&zbuf[fb * ZPAD + jl * 4];
            float zi = z4.x + sXZ[((par * 4 + 0) * 16 + fb) * XQ + jl];
            float zf = z4.y + sXZ[((par * 4 + 1) * 16 + fb) * XQ + jl];
            float zc = z4.z + sXZ[((par * 4 + 2) * 16 + fb) * XQ + jl];
            float zo = z4.w + sXZ[((par * 4 + 3) * 16 + fb) * XQ + jl];
            float ig = 1.f / (1.f + __expf(-zi));
            float fg = 1.f / (1.f + __expf(-zf));
            float og = 1.f / (1.f + __expf(-zo));
            float cc = fmaxf(zc, 0.f);
            cst = fg * cst + ig * cc;
            float h = og * fmaxf(cst, 0.f);
            __nv_bfloat16 hh = __float2bfloat16(h);
            __nv_bfloat16 hl = __float2bfloat16(h - __bfloat162float(hh));
            st16cg(&g_hxh[dir][bg][nxt][fb * HH + hc0 + jl], *(unsigned short*)&hh);
            st16cg(&g_hxl[dir][bg][nxt][fb * HH + hc0 + jl], *(unsigned short*)&hl);
            hist[((size_t)(bg * 16 + fb) * SS + spos) * HH + hc0 + jl] = h;
        }

        // ---- flag-based inter-CTA barrier (16 CTAs sharing (dir,bg))
        __threadfence();
        __syncthreads();
        if (t == 0)
            *(volatile unsigned*)&g_flag[dir][bg][cg] = (unsigned)(step + 1);
        if (t < 16) {
            volatile unsigned* f = &g_flag[dir][bg][t];
            unsigned tgt = (unsigned)(step + 1);
            while (*f < tgt) __nanosleep(20);
        }
        __syncthreads();
    }
#undef XZ_PREFETCH
}

// ---------------- phase 3: logits = (hf + hb).reshape(B,-1) @ Wd + bd ----------------
__global__ __launch_bounds__(256) void dense_out(
    const float* __restrict__ Wd, const float* __restrict__ bd, float* __restrict__ out)
{
    __shared__ float s0[256], s1[256];
    const int b = blockIdx.x, t = threadIdx.x;
    const float* hf = g_hf + (size_t)b * (SS * HH);
    const float* hb = g_hb + (size_t)b * (SS * HH);
    float a0 = 0.f, a1 = 0.f;
    for (int i = t * 4; i < SS * HH; i += 256 * 4) {
        float4 vf = *(const float4*)(hf + i);
        float4 vb = *(const float4*)(hb + i);
        float4 w0 = *(const float4*)(Wd + 2 * i);
        float4 w1 = *(const float4*)(Wd + 2 * i + 4);
        float v0 = vf.x + vb.x, v1 = vf.y + vb.y, v2 = vf.z + vb.z, v3 = vf.w + vb.w;
        a0 = fmaf(v0, w0.x, a0); a1 = fmaf(v0, w0.y, a1);
        a0 = fmaf(v1, w0.z, a0); a1 = fmaf(v1, w0.w, a1);
        a0 = fmaf(v2, w1.x, a0); a1 = fmaf(v2, w1.y, a1);
        a0 = fmaf(v3, w1.z, a0); a1 = fmaf(v3, w1.w, a1);
    }
    s0[t] = a0; s1[t] = a1;
    __syncthreads();
    for (int s = 128; s > 0; s >>= 1) {
        if (t < s) { s0[t] += s0[t + s]; s1[t] += s1[t + s]; }
        __syncthreads();
    }
    if (t == 0) {
        out[b * 2 + 0] = s0[0] + bd[0];
        out[b * 2 + 1] = s1[0] + bd[1];
    }
}

// ---------------- launcher ----------------
extern "C" void kernel_launch(void* const* d_in, const int* in_sizes, int n_in,
                              void* d_out, int out_size)
{
    const float* x  = (const float*)d_in[0];
    const float* kf = (const float*)d_in[1];
    const float* rf = (const float*)d_in[2];
    const float* bf = (const float*)d_in[3];
    const float* kb = (const float*)d_in[4];
    const float* rb = (const float*)d_in[5];
    const float* bbv= (const float*)d_in[6];
    const float* Wd = (const float*)d_in[7];
    const float* bd = (const float*)d_in[8];
    float* out = (float*)d_out;

    init_k<<<64, 256>>>();
    split_x<<<4096, 256>>>(x);
    split_w<<<1024, 256>>>(kf, kb);
    split_rec<<<512, 256>>>(rf, rb);

    cudaFuncSetAttribute(gemm_mma, cudaFuncAttributeMaxDynamicSharedMemorySize, GEMM_SMEM);
    gemm_mma<<<dim3(G4 / 128, MM / 128, 2), 256, GEMM_SMEM>>>(bf, bbv);

    cudaFuncSetAttribute(lstm_rec, cudaFuncAttributeMaxDynamicSharedMemorySize, LSTM_SMEM);
    lstm_rec<<<128, 256, LSTM_SMEM>>>();

    dense_out<<<BB, 256>>>(Wd, bd, out);
}

// round 14
// speedup vs baseline: 2.2145x; 2.2145x over previous
#include <cuda_runtime.h>
#include <cuda_bf16.h>
#include <cstdint>

// Problem constants
#define BB 64
#define SS 512
#define EE 768
#define HH 256
#define G4 1024    // 4*H
#define MM (BB*SS) // 32768 rows

// ---------------- scratch (device globals; no allocation allowed) ----------------
__device__ float g_xzf[MM * G4];        // x @ kernel_f + bias_f
__device__ float g_xzb[MM * G4];        // x @ kernel_b + bias_b
__device__ float g_hf[MM * HH];         // forward h history
__device__ float g_hb[MM * HH];         // backward h history (un-reversed)

// per-(dir, batch-group) h exchange ping-pong (bf16 hi/lo): [dir][bg][par][16*256]
__device__ __nv_bfloat16 g_hxh[2][4][2][16 * HH];
__device__ __nv_bfloat16 g_hxl[2][4][2][16 * HH];
__device__ unsigned g_bar2[2][4];       // per-(dir,bg) barrier counters

// bf16 split operands for input GEMM
__device__ __nv_bfloat16 g_xh[MM * EE];           // hi(x)
__device__ __nv_bfloat16 g_xl[MM * EE];           // lo(x)
__device__ __nv_bfloat16 g_wt[2][2][G4 * EE];     // [dir][hi/lo] W^T as [n][k]

// rec^T bf16 hi/lo: [dir][hi/lo][col(1024)][k(256)]
__device__ __nv_bfloat16 g_recT[2][2][G4 * HH];

// ---------------- PTX helpers ----------------
__device__ __forceinline__ uint32_t smem_u32(const void* p) {
    uint32_t a;
    asm("{ .reg .u64 t; cvta.to.shared.u64 t, %1; cvt.u32.u64 %0, t; }" : "=r"(a) : "l"(p));
    return a;
}
__device__ __forceinline__ void cp16(uint32_t s, const void* g) {
    asm volatile("cp.async.cg.shared.global [%0], [%1], 16;" :: "r"(s), "l"(g));
}
#define CP_COMMIT() asm volatile("cp.async.commit_group;" ::: "memory")
#define CP_WAIT0()  asm volatile("cp.async.wait_group 0;" ::: "memory")
#define CP_WAIT1()  asm volatile("cp.async.wait_group 1;" ::: "memory")

#define LDSM4(R, addr) \
    asm volatile("ldmatrix.sync.aligned.m8n8.x4.shared.b16 {%0,%1,%2,%3}, [%4];" \
        : "=r"((R)[0]), "=r"((R)[1]), "=r"((R)[2]), "=r"((R)[3]) : "r"(addr))

#define LDSM2(R, addr) \
    asm volatile("ldmatrix.sync.aligned.m8n8.x2.shared.b16 {%0,%1}, [%2];" \
        : "=r"((R)[0]), "=r"((R)[1]) : "r"(addr))

#define MMA16816(d, a, b) \
    asm volatile("mma.sync.aligned.m16n8k16.row.col.f32.bf16.bf16.f32 " \
        "{%0,%1,%2,%3}, {%4,%5,%6,%7}, {%8,%9}, {%0,%1,%2,%3};" \
        : "+f"((d)[0]), "+f"((d)[1]), "+f"((d)[2]), "+f"((d)[3]) \
        : "r"((a)[0]), "r"((a)[1]), "r"((a)[2]), "r"((a)[3]), "r"((b)[0]), "r"((b)[1]))

__device__ __forceinline__ void st16cg(void* p, unsigned short v) {
    asm volatile("st.global.cg.u16 [%0], %1;" :: "l"(p), "h"(v));
}

// ---------------- init: zero barriers + h exchange buffers ----------------
__global__ void init_k() {
    int i = blockIdx.x * blockDim.x + threadIdx.x;
    if (i < 8) (&g_bar2[0][0])[i] = 0u;
    int stride = gridDim.x * blockDim.x;
    __nv_bfloat16 z = __float2bfloat16(0.f);
    for (int k = i; k < 2 * 4 * 2 * 16 * HH; k += stride) {
        (&g_hxh[0][0][0][0])[k] = z;
        (&g_hxl[0][0][0][0])[k] = z;
    }
}

// ---------------- prep: bf16 hi/lo splits ----------------
__global__ __launch_bounds__(256) void split_x(const float* __restrict__ x) {
    int stride = gridDim.x * blockDim.x;
    const int n4 = MM * EE / 4;
    for (int i = blockIdx.x * blockDim.x + threadIdx.x; i < n4; i += stride) {
        float4 v = *(const float4*)(x + i * 4);
        __nv_bfloat16 h0 = __float2bfloat16(v.x), h1 = __float2bfloat16(v.y);
        __nv_bfloat16 h2 = __float2bfloat16(v.z), h3 = __float2bfloat16(v.w);
        __nv_bfloat162* dh = (__nv_bfloat162*)(g_xh + i * 4);
        __nv_bfloat162* dl = (__nv_bfloat162*)(g_xl + i * 4);
        dh[0] = __nv_bfloat162(h0, h1);
        dh[1] = __nv_bfloat162(h2, h3);
        dl[0] = __nv_bfloat162(__float2bfloat16(v.x - __bfloat162float(h0)),
                               __float2bfloat16(v.y - __bfloat162float(h1)));
        dl[1] = __nv_bfloat162(__float2bfloat16(v.z - __bfloat162float(h2)),
                               __float2bfloat16(v.w - __bfloat162float(h3)));
    }
}

// fused W^T + rec^T split (independent elementwise regions)
__global__ __launch_bounds__(256) void split_wr(
    const float* __restrict__ kf, const float* __restrict__ kb,
    const float* __restrict__ rf, const float* __restrict__ rb)
{
    int stride = gridDim.x * blockDim.x;
    const int NW = EE * G4, NR = HH * G4;
    for (int i = blockIdx.x * blockDim.x + threadIdx.x; i < NW + NR; i += stride) {
        if (i < NW) {
            int n = i & (G4 - 1), k = i >> 10;
            float vf = kf[i], vb = kb[i];
            __nv_bfloat16 hf16 = __float2bfloat16(vf);
            __nv_bfloat16 hb16 = __float2bfloat16(vb);
            g_wt[0][0][n * EE + k] = hf16;
            g_wt[0][1][n * EE + k] = __float2bfloat16(vf - __bfloat162float(hf16));
            g_wt[1][0][n * EE + k] = hb16;
            g_wt[1][1][n * EE + k] = __float2bfloat16(vb - __bfloat162float(hb16));
        } else {
            int j = i - NW;
            int k = j >> 10, col = j & (G4 - 1);
            float vf = rf[j], vb = rb[j];
            __nv_bfloat16 hf16 = __float2bfloat16(vf);
            __nv_bfloat16 hb16 = __float2bfloat16(vb);
            g_recT[0][0][col * HH + k] = hf16;
            g_recT[0][1][col * HH + k] = __float2bfloat16(vf - __bfloat162float(hf16));
            g_recT[1][0][col * HH + k] = hb16;
            g_recT[1][1][col * HH + k] = __float2bfloat16(vb - __bfloat162float(hb16));
        }
    }
}

// ---------------- phase 1: mma.sync bf16 GEMM  xz = x @ W + bias ----------------
// R11 shape (proven ~930us): 3-term split over K' = 3*768: chunks [0,12)=Ah*Bh,
// [12,24)=Al*Bh, [24,36)=Ah*Bl. CTA tile 128x128, BK=64, 256 thr, 2-stage cp.async.
#define NKCH 36
#define GPAD 72
#define GEMM_SMEM (2 * 2 * 128 * GPAD * 2)   // 147456 B dynamic

__global__ __launch_bounds__(256) void gemm_mma(
    const float* __restrict__ bias_f, const float* __restrict__ bias_b)
{
    extern __shared__ __nv_bfloat16 gsm[];
    __nv_bfloat16* sA = gsm;                  // [2][128][GPAD]
    __nv_bfloat16* sB = gsm + 2 * 128 * GPAD; // [2][128][GPAD]

    const int t = threadIdx.x, lane = t & 31, w = t >> 5;
    const int dir = blockIdx.z;
    const int m0 = blockIdx.y * 128;
    const int n0 = blockIdx.x * 128;

    const __nv_bfloat16* wth = &g_wt[dir][0][0];
    const __nv_bfloat16* wtl = &g_wt[dir][1][0];
    const float* bias = dir ? bias_b : bias_f;
    float* out = dir ? g_xzb : g_xzf;

    const uint32_t sAu = smem_u32(sA);
    const uint32_t sBu = smem_u32(sB);

    float acc[2][8][4];
#pragma unroll
    for (int i = 0; i < 2; i++)
#pragma unroll
        for (int j = 0; j < 8; j++)
#pragma unroll
            for (int k = 0; k < 4; k++) acc[i][j][k] = 0.f;

    const int lrow = t >> 3, lcol8 = t & 7;

    const int wm = (w & 3) * 32, wn = (w >> 2) * 64;
    const int aRow = wm + (lane & 15);
    const int aCol = (lane >> 4) * 8;
    const int bRow = wn + (lane & 7) + ((lane & 16) ? 8 : 0);
    const int bCol = ((lane >> 3) & 1) * 8;

#define LOAD_CHUNK(kc, buf) do {                                                   \
    int p_ = (kc) / 12, kk_ = (kc) - p_ * 12;                                      \
    const __nv_bfloat16* Ag_ = (p_ == 1) ? g_xl : g_xh;                            \
    const __nv_bfloat16* Bg_ = (p_ == 2) ? wtl : wth;                              \
    _Pragma("unroll")                                                              \
    for (int i_ = 0; i_ < 4; i_++) {                                               \
        int row_ = lrow + 32 * i_;                                                 \
        cp16(sAu + (((buf) * 128 + row_) * GPAD + lcol8 * 8) * 2,                  \
             Ag_ + (size_t)(m0 + row_) * EE + kk_ * 64 + lcol8 * 8);               \
        cp16(sBu + (((buf) * 128 + row_) * GPAD + lcol8 * 8) * 2,                  \
             Bg_ + (size_t)(n0 + row_) * EE + kk_ * 64 + lcol8 * 8);               \
    }                                                                              \
} while (0)

    LOAD_CHUNK(0, 0);
    CP_COMMIT();

    for (int kc = 0; kc < NKCH; kc++) {
        const int buf = kc & 1;
        CP_WAIT0();
        __syncthreads();
        if (kc + 1 < NKCH) { LOAD_CHUNK(kc + 1, buf ^ 1); CP_COMMIT(); }

#pragma unroll
        for (int k16 = 0; k16 < 64; k16 += 16) {
            uint32_t a[2][4];
#pragma unroll
            for (int mt = 0; mt < 2; mt++)
                LDSM4(a[mt], sAu + ((buf * 128 + aRow + mt * 16) * GPAD + k16 + aCol) * 2);
            uint32_t b[8][2];
#pragma unroll
            for (int i = 0; i < 4; i++) {
                uint32_t r[4];
                LDSM4(r, sBu + ((buf * 128 + bRow + i * 16) * GPAD + k16 + bCol) * 2);
                b[2 * i][0] = r[0]; b[2 * i][1] = r[1];
                b[2 * i + 1][0] = r[2]; b[2 * i + 1][1] = r[3];
            }
#pragma unroll
            for (int mt = 0; mt < 2; mt++)
#pragma unroll
                for (int nt = 0; nt < 8; nt++)
                    MMA16816(acc[mt][nt], a[mt], b[nt]);
        }
        __syncthreads();
    }
#undef LOAD_CHUNK

#pragma unroll
    for (int nt = 0; nt < 8; nt++) {
        const int col = n0 + wn + nt * 8 + (lane & 3) * 2;
        const float b0 = __ldg(bias + col), b1 = __ldg(bias + col + 1);
#pragma unroll
        for (int mt = 0; mt < 2; mt++) {
            const int r0 = m0 + wm + mt * 16 + (lane >> 2);
            float2 v0 = make_float2(acc[mt][nt][0] + b0, acc[mt][nt][1] + b1);
            float2 v1 = make_float2(acc[mt][nt][2] + b0, acc[mt][nt][3] + b1);
            *(float2*)(out + (size_t)r0 * G4 + col) = v0;
            *(float2*)(out + (size_t)(r0 + 8) * G4 + col) = v1;
        }
    }
}

// ---------------- phase 2: persistent recurrence, batch-split HMMA ----------------
// Grid: 128 CTAs = 2 dirs x 4 batch-groups(16 batches) x 16 col-groups(16 h-cols).
// Sync domain = 16 CTAs sharing (dir,bg); atomic-counter barrier (proven).
#define RPAD 264
#define XQ 20
#define ZPAD 68
#define SREC_SZ  (2 * 64 * RPAD * 2)                 // 67584
#define SH_OFF   SREC_SZ
#define SH_SZ    (2 * 16 * RPAD * 2)                 // 16896
#define SXZ_OFF  (SH_OFF + SH_SZ)
#define SXZ_SZ   (2 * 4 * 16 * XQ * 4)               // 10240
#define ZB_OFF   (SXZ_OFF + SXZ_SZ)
#define ZB_SZ    (16 * ZPAD * 4)                     // 4352
#define LSTM_SMEM (ZB_OFF + ZB_SZ)                   // 99072

__global__ __launch_bounds__(256) void lstm_rec()
{
    extern __shared__ char smem[];
    __nv_bfloat16* sRec = (__nv_bfloat16*)(smem);            // [2][64][RPAD]
    __nv_bfloat16* sH   = (__nv_bfloat16*)(smem + SH_OFF);   // [2][16][RPAD]
    float*         sXZ  = (float*)(smem + SXZ_OFF);          // [2][4][16][XQ]
    float*         zbuf = (float*)(smem + ZB_OFF);           // [16][ZPAD]

    const int t = threadIdx.x, lane = t & 31, w = t >> 5;
    const int bx  = blockIdx.x;
    const int dir = bx >> 6;
    const int bg  = (bx >> 4) & 3;
    const int cg  = bx & 15;
    const int hc0 = cg * 16;

    const float* xz = dir ? g_xzb : g_xzf;
    float*     hist = dir ? g_hb  : g_hf;

    const uint32_t sRu  = smem_u32(sRec);
    const uint32_t sHu  = smem_u32(sH);
    const uint32_t sXZu = smem_u32(sXZ);

    // ---- load rec^T slice: sRec[p][lc][k], gate col = (lc&3)*256 + hc0 + (lc>>2)
    for (int seg = t; seg < 4096; seg += 256) {          // 2p x 64lc x 32segs
        int p = seg >> 11, rem = seg & 2047;
        int lc = rem >> 5, s = rem & 31;
        int col = (lc & 3) * HH + hc0 + (lc >> 2);
        uint4 v = *(const uint4*)(&g_recT[dir][p][0] + (size_t)col * HH + s * 8);
        *(uint4*)&sRec[(p * 64 + lc) * RPAD + s * 8] = v;
    }

    // ---- fragment addresses (warp w owns lc [w*8, w*8+8))
    const uint32_t aBaseH = sHu + (uint32_t)((lane & 15) * RPAD + (lane >> 4) * 8) * 2;
    const uint32_t aBaseL = aBaseH + 16 * RPAD * 2;
    const uint32_t bBaseH = sRu + (uint32_t)((w * 8 + (lane & 7)) * RPAD
                                             + ((lane >> 3) & 1) * 8) * 2;
    const uint32_t bBaseL = bBaseH + 64 * RPAD * 2;

    // gate-thread mapping: fb = t&15 (batch), jl = t>>4 (one h-col each)
    const int fb = t & 15, jl = t >> 4;
    float cst = 0.f;

    // ---- xz prefetch: 256 16B segs, 1/thread: q = t>>6, b = (t>>2)&15, sg = t&3
    const int pq = t >> 6, pfb = (t >> 2) & 15, psg = t & 3;

#define XZ_PREFETCH(spos, buf) \
    cp16(sXZu + ((((buf) * 4 + pq) * 16 + pfb) * XQ + psg * 4) * 4, \
         xz + ((size_t)(bg * 16 + pfb) * SS + (spos)) * G4 + pq * HH + hc0 + psg * 4)

    {
        int spos0 = dir ? (SS - 1) : 0;
        XZ_PREFETCH(spos0, 0);
        CP_COMMIT();
    }
    __syncthreads();

    for (int step = 0; step < SS; step++) {
        const int par = step & 1;

        // ---- load h (hi/lo) into sH: 2p x 16rows x 32segs = 1024 segs
        const __nv_bfloat16* srcH = &g_hxh[dir][bg][par][0];
        const __nv_bfloat16* srcL = &g_hxl[dir][bg][par][0];
#pragma unroll
        for (int i = 0; i < 4; i++) {
            int seg = t + 256 * i;
            int p = seg >> 9, rem = seg & 511;
            int row = rem >> 5, s = rem & 31;
            uint4 v = __ldcg((const uint4*)((p ? srcL : srcH) + row * HH + s * 8));
            *(uint4*)&sH[(p * 16 + row) * RPAD + s * 8] = v;
        }

        // ---- prefetch xz for next step
        if (step + 1 < SS) {
            int spos1 = dir ? (SS - 2 - step) : (step + 1);
            XZ_PREFETCH(spos1, (step + 1) & 1);
            CP_COMMIT();
        }
        __syncthreads();

        // ---- z = h @ recT (3-term bf16 split), warp tile M16 x N8
        float aHH[4], aLH[4], aHL[4];
#pragma unroll
        for (int k = 0; k < 4; k++) { aHH[k] = 0.f; aLH[k] = 0.f; aHL[k] = 0.f; }

#pragma unroll
        for (int k16 = 0; k16 < 256; k16 += 16) {
            const uint32_t ko = (uint32_t)k16 * 2;
            uint32_t ah[4], al[4], bh[2], bl[2];
            LDSM4(ah, aBaseH + ko);
            LDSM4(al, aBaseL + ko);
            LDSM2(bh, bBaseH + ko);
            LDSM2(bl, bBaseL + ko);
            MMA16816(aHH, ah, bh);
            MMA16816(aLH, al, bh);
            MMA16816(aHL, ah, bl);
        }

        // ---- stage z to smem (sum split terms)
        {
            const int col = w * 8 + (lane & 3) * 2;
            const int row = lane >> 2;
            float z0 = aHH[0] + aLH[0] + aHL[0];
            float z1 = aHH[1] + aLH[1] + aHL[1];
            float z2 = aHH[2] + aLH[2] + aHL[2];
            float z3 = aHH[3] + aLH[3] + aHL[3];
            *(float2*)&zbuf[row * ZPAD + col] = make_float2(z0, z1);
            *(float2*)&zbuf[(row + 8) * ZPAD + col] = make_float2(z2, z3);
        }
        if (step + 1 < SS) { CP_WAIT1(); } else { CP_WAIT0(); }
        __syncthreads();

        // ---- gates, state update, publish h (one h-col per thread)
        {
            const int spos = dir ? (SS - 1 - step) : step;
            const int nxt = par ^ 1;
            float4 z4 = *(const float4*)&zbuf[fb * ZPAD + jl * 4];
            float zi = z4.x + sXZ[((par * 4 + 0) * 16 + fb) * XQ + jl];
            float zf = z4.y + sXZ[((par * 4 + 1) * 16 + fb) * XQ + jl];
            float zc = z4.z + sXZ[((par * 4 + 2) * 16 + fb) * XQ + jl];
            float zo = z4.w + sXZ[((par * 4 + 3) * 16 + fb) * XQ + jl];
            float ig = 1.f / (1.f + __expf(-zi));
            float fg = 1.f / (1.f + __expf(-zf));
            float og = 1.f / (1.f + __expf(-zo));
            float cc = fmaxf(zc, 0.f);
            cst = fg * cst + ig * cc;
            float h = og * fmaxf(cst, 0.f);
            __nv_bfloat16 hh = __float2bfloat16(h);
            __nv_bfloat16 hl = __float2bfloat16(h - __bfloat162float(hh));
            st16cg(&g_hxh[dir][bg][nxt][fb * HH + hc0 + jl], *(unsigned short*)&hh);
            st16cg(&g_hxl[dir][bg][nxt][fb * HH + hc0 + jl], *(unsigned short*)&hl);
            hist[((size_t)(bg * 16 + fb) * SS + spos) * HH + hc0 + jl] = h;
        }

        // ---- inter-CTA barrier (16 CTAs sharing (dir,bg)) — atomic counter (proven)
        __threadfence();
        __syncthreads();
        if (t == 0) {
            atomicAdd(&g_bar2[dir][bg], 1u);
            unsigned tgt = 16u * (unsigned)(step + 1);
            while (*((volatile unsigned*)&g_bar2[dir][bg]) < tgt) __nanosleep(20);
        }
        __syncthreads();
    }
#undef XZ_PREFETCH
}

// ---------------- phase 3: logits = (hf + hb).reshape(B,-1) @ Wd + bd ----------------
__global__ __launch_bounds__(256) void dense_out(
    const float* __restrict__ Wd, const float* __restrict__ bd, float* __restrict__ out)
{
    __shared__ float s0[256], s1[256];
    const int b = blockIdx.x, t = threadIdx.x;
    const float* hf = g_hf + (size_t)b * (SS * HH);
    const float* hb = g_hb + (size_t)b * (SS * HH);
    float a0 = 0.f, a1 = 0.f;
    for (int i = t * 4; i < SS * HH; i += 256 * 4) {
        float4 vf = *(const float4*)(hf + i);
        float4 vb = *(const float4*)(hb + i);
        float4 w0 = *(const float4*)(Wd + 2 * i);
        float4 w1 = *(const float4*)(Wd + 2 * i + 4);
        float v0 = vf.x + vb.x, v1 = vf.y + vb.y, v2 = vf.z + vb.z, v3 = vf.w + vb.w;
        a0 = fmaf(v0, w0.x, a0); a1 = fmaf(v0, w0.y, a1);
        a0 = fmaf(v1, w0.z, a0); a1 = fmaf(v1, w0.w, a1);
        a0 = fmaf(v2, w1.x, a0); a1 = fmaf(v2, w1.y, a1);
        a0 = fmaf(v3, w1.z, a0); a1 = fmaf(v3, w1.w, a1);
    }
    s0[t] = a0; s1[t] = a1;
    __syncthreads();
    for (int s = 128; s > 0; s >>= 1) {
        if (t < s) { s0[t] += s0[t + s]; s1[t] += s1[t + s]; }
        __syncthreads();
    }
    if (t == 0) {
        out[b * 2 + 0] = s0[0] + bd[0];
        out[b * 2 + 1] = s1[0] + bd[1];
    }
}

// ---------------- launcher ----------------
extern "C" void kernel_launch(void* const* d_in, const int* in_sizes, int n_in,
                              void* d_out, int out_size)
{
    const float* x  = (const float*)d_in[0];
    const float* kf = (const float*)d_in[1];
    const float* rf = (const float*)d_in[2];
    const float* bf = (const float*)d_in[3];
    const float* kb = (const float*)d_in[4];
    const float* rb = (const float*)d_in[5];
    const float* bbv= (const float*)d_in[6];
    const float* Wd = (const float*)d_in[7];
    const float* bd = (const float*)d_in[8];
    float* out = (float*)d_out;

    init_k<<<64, 256>>>();
    split_x<<<4096, 256>>>(x);
    split_wr<<<1280, 256>>>(kf, kb, rf, rb);

    cudaFuncSetAttribute(gemm_mma, cudaFuncAttributeMaxDynamicSharedMemorySize, GEMM_SMEM);
    gemm_mma<<<dim3(G4 / 128, MM / 128, 2), 256, GEMM_SMEM>>>(bf, bbv);

    cudaFuncSetAttribute(lstm_rec, cudaFuncAttributeMaxDynamicSharedMemorySize, LSTM_SMEM);
    lstm_rec<<<128, 256, LSTM_SMEM>>>();

    dense_out<<<BB, 256>>>(Wd, bd, out);
}

// round 15
// speedup vs baseline: 2.3593x; 1.0654x over previous
#include <cuda_runtime.h>
#include <cuda_bf16.h>
#include <cstdint>

// Problem constants
#define BB 64
#define SS 512
#define EE 768
#define HH 256
#define G4 1024    // 4*H
#define MM (BB*SS) // 32768 rows

// ---------------- scratch (device globals; no allocation allowed) ----------------
__device__ float g_xzf[MM * G4];        // x @ kernel_f + bias_f
__device__ float g_xzb[MM * G4];        // x @ kernel_b + bias_b
__device__ float g_hf[MM * HH];         // forward h history
__device__ float g_hb[MM * HH];         // backward h history (un-reversed)

// per-(dir, batch-group) h exchange ping-pong (bf16 hi/lo): [dir][bg][par][16*256]
__device__ __nv_bfloat16 g_hxh[2][4][2][16 * HH];
__device__ __nv_bfloat16 g_hxl[2][4][2][16 * HH];
__device__ unsigned g_bar2[2][4];       // per-(dir,bg) barrier counters

// bf16 split operands for input GEMM
__device__ __nv_bfloat16 g_xh[MM * EE];           // hi(x)
__device__ __nv_bfloat16 g_xl[MM * EE];           // lo(x)
__device__ __nv_bfloat16 g_wt[2][2][G4 * EE];     // [dir][hi/lo] W^T as [n][k]

// rec^T bf16 hi/lo: [dir][hi/lo][col(1024)][k(256)]
__device__ __nv_bfloat16 g_recT[2][2][G4 * HH];

// ---------------- PTX helpers ----------------
__device__ __forceinline__ uint32_t smem_u32(const void* p) {
    uint32_t a;
    asm("{ .reg .u64 t; cvta.to.shared.u64 t, %1; cvt.u32.u64 %0, t; }" : "=r"(a) : "l"(p));
    return a;
}
__device__ __forceinline__ void cp16(uint32_t s, const void* g) {
    asm volatile("cp.async.cg.shared.global [%0], [%1], 16;" :: "r"(s), "l"(g));
}
#define CP_COMMIT() asm volatile("cp.async.commit_group;" ::: "memory")
#define CP_WAIT0()  asm volatile("cp.async.wait_group 0;" ::: "memory")
#define CP_WAIT1()  asm volatile("cp.async.wait_group 1;" ::: "memory")

#define LDSM4(R, addr) \
    asm volatile("ldmatrix.sync.aligned.m8n8.x4.shared.b16 {%0,%1,%2,%3}, [%4];" \
        : "=r"((R)[0]), "=r"((R)[1]), "=r"((R)[2]), "=r"((R)[3]) : "r"(addr))

#define LDSM2(R, addr) \
    asm volatile("ldmatrix.sync.aligned.m8n8.x2.shared.b16 {%0,%1}, [%2];" \
        : "=r"((R)[0]), "=r"((R)[1]) : "r"(addr))

#define MMA16816(d, a, b) \
    asm volatile("mma.sync.aligned.m16n8k16.row.col.f32.bf16.bf16.f32 " \
        "{%0,%1,%2,%3}, {%4,%5,%6,%7}, {%8,%9}, {%0,%1,%2,%3};" \
        : "+f"((d)[0]), "+f"((d)[1]), "+f"((d)[2]), "+f"((d)[3]) \
        : "r"((a)[0]), "r"((a)[1]), "r"((a)[2]), "r"((a)[3]), "r"((b)[0]), "r"((b)[1]))

__device__ __forceinline__ void st16cg(void* p, unsigned short v) {
    asm volatile("st.global.cg.u16 [%0], %1;" :: "l"(p), "h"(v));
}

// ---------------- init: zero barriers + h exchange buffers ----------------
__global__ void init_k() {
    int i = blockIdx.x * blockDim.x + threadIdx.x;
    if (i < 8) (&g_bar2[0][0])[i] = 0u;
    int stride = gridDim.x * blockDim.x;
    __nv_bfloat16 z = __float2bfloat16(0.f);
    for (int k = i; k < 2 * 4 * 2 * 16 * HH; k += stride) {
        (&g_hxh[0][0][0][0])[k] = z;
        (&g_hxl[0][0][0][0])[k] = z;
    }
}

// ---------------- prep: bf16 hi/lo splits ----------------
__global__ __launch_bounds__(256) void split_x(const float* __restrict__ x) {
    int stride = gridDim.x * blockDim.x;
    const int n4 = MM * EE / 4;
    for (int i = blockIdx.x * blockDim.x + threadIdx.x; i < n4; i += stride) {
        float4 v = *(const float4*)(x + i * 4);
        __nv_bfloat16 h0 = __float2bfloat16(v.x), h1 = __float2bfloat16(v.y);
        __nv_bfloat16 h2 = __float2bfloat16(v.z), h3 = __float2bfloat16(v.w);
        __nv_bfloat162* dh = (__nv_bfloat162*)(g_xh + i * 4);
        __nv_bfloat162* dl = (__nv_bfloat162*)(g_xl + i * 4);
        dh[0] = __nv_bfloat162(h0, h1);
        dh[1] = __nv_bfloat162(h2, h3);
        dl[0] = __nv_bfloat162(__float2bfloat16(v.x - __bfloat162float(h0)),
                               __float2bfloat16(v.y - __bfloat162float(h1)));
        dl[1] = __nv_bfloat162(__float2bfloat16(v.z - __bfloat162float(h2)),
                               __float2bfloat16(v.w - __bfloat162float(h3)));
    }
}

// fused W^T + rec^T split (independent elementwise regions)
__global__ __launch_bounds__(256) void split_wr(
    const float* __restrict__ kf, const float* __restrict__ kb,
    const float* __restrict__ rf, const float* __restrict__ rb)
{
    int stride = gridDim.x * blockDim.x;
    const int NW = EE * G4, NR = HH * G4;
    for (int i = blockIdx.x * blockDim.x + threadIdx.x; i < NW + NR; i += stride) {
        if (i < NW) {
            int n = i & (G4 - 1), k = i >> 10;
            float vf = kf[i], vb = kb[i];
            __nv_bfloat16 hf16 = __float2bfloat16(vf);
            __nv_bfloat16 hb16 = __float2bfloat16(vb);
            g_wt[0][0][n * EE + k] = hf16;
            g_wt[0][1][n * EE + k] = __float2bfloat16(vf - __bfloat162float(hf16));
            g_wt[1][0][n * EE + k] = hb16;
            g_wt[1][1][n * EE + k] = __float2bfloat16(vb - __bfloat162float(hb16));
        } else {
            int j = i - NW;
            int k = j >> 10, col = j & (G4 - 1);
            float vf = rf[j], vb = rb[j];
            __nv_bfloat16 hf16 = __float2bfloat16(vf);
            __nv_bfloat16 hb16 = __float2bfloat16(vb);
            g_recT[0][0][col * HH + k] = hf16;
            g_recT[0][1][col * HH + k] = __float2bfloat16(vf - __bfloat162float(hf16));
            g_recT[1][0][col * HH + k] = hb16;
            g_recT[1][1][col * HH + k] = __float2bfloat16(vb - __bfloat162float(hb16));
        }
    }
}

// ---------------- phase 1: mma.sync bf16 GEMM  xz = x @ W + bias ----------------
// 3-term split over K' = 3*768: chunks [0,12)=Ah*Bh, [12,24)=Al*Bh, [24,36)=Ah*Bl.
// CTA tile 128x128, BK=64, 256 thr, 3-stage cp.async (CP_WAIT1 = 1 chunk slack).
#define NKCH 36
#define GPAD 72
#define GSTAGE (2 * 128 * GPAD)              // bf16 elems per stage (A+B)
#define GEMM_SMEM (3 * GSTAGE * 2)           // 221184 B dynamic

__global__ __launch_bounds__(256) void gemm_mma(
    const float* __restrict__ bias_f, const float* __restrict__ bias_b)
{
    extern __shared__ __nv_bfloat16 gsm[];
    // stage s: A at gsm + s*GSTAGE, B at gsm + s*GSTAGE + 128*GPAD

    const int t = threadIdx.x, lane = t & 31, w = t >> 5;
    const int dir = blockIdx.z;
    const int m0 = blockIdx.y * 128;
    const int n0 = blockIdx.x * 128;

    const __nv_bfloat16* wth = &g_wt[dir][0][0];
    const __nv_bfloat16* wtl = &g_wt[dir][1][0];
    const float* bias = dir ? bias_b : bias_f;
    float* out = dir ? g_xzb : g_xzf;

    const uint32_t sBase = smem_u32(gsm);

    float acc[2][8][4];
#pragma unroll
    for (int i = 0; i < 2; i++)
#pragma unroll
        for (int j = 0; j < 8; j++)
#pragma unroll
            for (int k = 0; k < 4; k++) acc[i][j][k] = 0.f;

    const int lrow = t >> 3, lcol8 = t & 7;

    const int wm = (w & 3) * 32, wn = (w >> 2) * 64;
    const int aRow = wm + (lane & 15);
    const int aCol = (lane >> 4) * 8;
    const int bRow = wn + (lane & 7) + ((lane & 16) ? 8 : 0);
    const int bCol = ((lane >> 3) & 1) * 8;

#define LOAD_CHUNK(kc, buf) do {                                                   \
    int p_ = (kc) / 12, kk_ = (kc) - p_ * 12;                                      \
    const __nv_bfloat16* Ag_ = (p_ == 1) ? g_xl : g_xh;                            \
    const __nv_bfloat16* Bg_ = (p_ == 2) ? wtl : wth;                              \
    uint32_t sA_ = sBase + (uint32_t)(buf) * GSTAGE * 2;                           \
    uint32_t sB_ = sA_ + 128 * GPAD * 2;                                           \
    _Pragma("unroll")                                                              \
    for (int i_ = 0; i_ < 4; i_++) {                                               \
        int row_ = lrow + 32 * i_;                                                 \
        cp16(sA_ + (uint32_t)(row_ * GPAD + lcol8 * 8) * 2,                        \
             Ag_ + (size_t)(m0 + row_) * EE + kk_ * 64 + lcol8 * 8);               \
        cp16(sB_ + (uint32_t)(row_ * GPAD + lcol8 * 8) * 2,                        \
             Bg_ + (size_t)(n0 + row_) * EE + kk_ * 64 + lcol8 * 8);               \
    }                                                                              \
} while (0)

    LOAD_CHUNK(0, 0);
    CP_COMMIT();
    LOAD_CHUNK(1, 1);
    CP_COMMIT();

    int buf = 0;
    for (int kc = 0; kc < NKCH; kc++) {
        if (kc + 1 < NKCH) { CP_WAIT1(); } else { CP_WAIT0(); }
        __syncthreads();   // all threads see stage `buf` complete; prev compute done
        if (kc + 2 < NKCH) {
            int nb = buf + 2; if (nb >= 3) nb -= 3;
            LOAD_CHUNK(kc + 2, nb);
            CP_COMMIT();
        }

        const uint32_t sAu = sBase + (uint32_t)buf * GSTAGE * 2;
        const uint32_t sBu = sAu + 128 * GPAD * 2;
#pragma unroll
        for (int k16 = 0; k16 < 64; k16 += 16) {
            uint32_t a[2][4];
#pragma unroll
            for (int mt = 0; mt < 2; mt++)
                LDSM4(a[mt], sAu + ((aRow + mt * 16) * GPAD + k16 + aCol) * 2);
            uint32_t b[8][2];
#pragma unroll
            for (int i = 0; i < 4; i++) {
                uint32_t r[4];
                LDSM4(r, sBu + ((bRow + i * 16) * GPAD + k16 + bCol) * 2);
                b[2 * i][0] = r[0]; b[2 * i][1] = r[1];
                b[2 * i + 1][0] = r[2]; b[2 * i + 1][1] = r[3];
            }
#pragma unroll
            for (int mt = 0; mt < 2; mt++)
#pragma unroll
                for (int nt = 0; nt < 8; nt++)
                    MMA16816(acc[mt][nt], a[mt], b[nt]);
        }
        if (++buf == 3) buf = 0;
    }
#undef LOAD_CHUNK

#pragma unroll
    for (int nt = 0; nt < 8; nt++) {
        const int col = n0 + wn + nt * 8 + (lane & 3) * 2;
        const float b0 = __ldg(bias + col), b1 = __ldg(bias + col + 1);
#pragma unroll
        for (int mt = 0; mt < 2; mt++) {
            const int r0 = m0 + wm + mt * 16 + (lane >> 2);
            float2 v0 = make_float2(acc[mt][nt][0] + b0, acc[mt][nt][1] + b1);
            float2 v1 = make_float2(acc[mt][nt][2] + b0, acc[mt][nt][3] + b1);
            *(float2*)(out + (size_t)r0 * G4 + col) = v0;
            *(float2*)(out + (size_t)(r0 + 8) * G4 + col) = v1;
        }
    }
}

// ---------------- phase 2: persistent recurrence, batch-split HMMA ----------------
// Grid: 128 CTAs = 2 dirs x 4 batch-groups(16 batches) x 16 col-groups(16 h-cols).
// Sync domain = 16 CTAs sharing (dir,bg); atomic-counter barrier (proven).
// Gate-thread mapping now fb = t>>4, jl = t&15 -> COALESCED h publish.
#define RPAD 264
#define XQ 20
#define ZPAD 68
#define SREC_SZ  (2 * 64 * RPAD * 2)                 // 67584
#define SH_OFF   SREC_SZ
#define SH_SZ    (2 * 16 * RPAD * 2)                 // 16896
#define SXZ_OFF  (SH_OFF + SH_SZ)
#define SXZ_SZ   (2 * 4 * 16 * XQ * 4)               // 10240
#define ZB_OFF   (SXZ_OFF + SXZ_SZ)
#define ZB_SZ    (16 * ZPAD * 4)                     // 4352
#define LSTM_SMEM (ZB_OFF + ZB_SZ)                   // 99072

__global__ __launch_bounds__(256) void lstm_rec()
{
    extern __shared__ char smem[];
    __nv_bfloat16* sRec = (__nv_bfloat16*)(smem);            // [2][64][RPAD]
    __nv_bfloat16* sH   = (__nv_bfloat16*)(smem + SH_OFF);   // [2][16][RPAD]
    float*         sXZ  = (float*)(smem + SXZ_OFF);          // [2][4][16][XQ]
    float*         zbuf = (float*)(smem + ZB_OFF);           // [16][ZPAD]

    const int t = threadIdx.x, lane = t & 31, w = t >> 5;
    const int bx  = blockIdx.x;
    const int dir = bx >> 6;
    const int bg  = (bx >> 4) & 3;
    const int cg  = bx & 15;
    const int hc0 = cg * 16;

    const float* xz = dir ? g_xzb : g_xzf;
    float*     hist = dir ? g_hb  : g_hf;

    const uint32_t sRu  = smem_u32(sRec);
    const uint32_t sHu  = smem_u32(sH);
    const uint32_t sXZu = smem_u32(sXZ);

    // ---- load rec^T slice: sRec[p][lc][k], gate col = (lc&3)*256 + hc0 + (lc>>2)
    for (int seg = t; seg < 4096; seg += 256) {          // 2p x 64lc x 32segs
        int p = seg >> 11, rem = seg & 2047;
        int lc = rem >> 5, s = rem & 31;
        int col = (lc & 3) * HH + hc0 + (lc >> 2);
        uint4 v = *(const uint4*)(&g_recT[dir][p][0] + (size_t)col * HH + s * 8);
        *(uint4*)&sRec[(p * 64 + lc) * RPAD + s * 8] = v;
    }

    // ---- fragment addresses (warp w owns lc [w*8, w*8+8))
    const uint32_t aBaseH = sHu + (uint32_t)((lane & 15) * RPAD + (lane >> 4) * 8) * 2;
    const uint32_t aBaseL = aBaseH + 16 * RPAD * 2;
    const uint32_t bBaseH = sRu + (uint32_t)((w * 8 + (lane & 7)) * RPAD
                                             + ((lane >> 3) & 1) * 8) * 2;
    const uint32_t bBaseL = bBaseH + 64 * RPAD * 2;

    // gate-thread mapping (COALESCED): fb = t>>4 (batch), jl = t&15 (h-col)
    const int fb = t >> 4, jl = t & 15;
    float cst = 0.f;

    // ---- xz prefetch: 256 16B segs, 1/thread: q = t>>6, b = (t>>2)&15, sg = t&3
    const int pq = t >> 6, pfb = (t >> 2) & 15, psg = t & 3;

#define XZ_PREFETCH(spos, buf) \
    cp16(sXZu + ((((buf) * 4 + pq) * 16 + pfb) * XQ + psg * 4) * 4, \
         xz + ((size_t)(bg * 16 + pfb) * SS + (spos)) * G4 + pq * HH + hc0 + psg * 4)

    {
        int spos0 = dir ? (SS - 1) : 0;
        XZ_PREFETCH(spos0, 0);
        CP_COMMIT();
    }
    __syncthreads();

    for (int step = 0; step < SS; step++) {
        const int par = step & 1;

        // ---- load h (hi/lo) into sH: 2p x 16rows x 32segs = 1024 segs
        const __nv_bfloat16* srcH = &g_hxh[dir][bg][par][0];
        const __nv_bfloat16* srcL = &g_hxl[dir][bg][par][0];
#pragma unroll
        for (int i = 0; i < 4; i++) {
            int seg = t + 256 * i;
            int p = seg >> 9, rem = seg & 511;
            int row = rem >> 5, s = rem & 31;
            uint4 v = __ldcg((const uint4*)((p ? srcL : srcH) + row * HH + s * 8));
            *(uint4*)&sH[(p * 16 + row) * RPAD + s * 8] = v;
        }

        // ---- prefetch xz for next step
        if (step + 1 < SS) {
            int spos1 = dir ? (SS - 2 - step) : (step + 1);
            XZ_PREFETCH(spos1, (step + 1) & 1);
            CP_COMMIT();
        }
        __syncthreads();

        // ---- z = h @ recT (3-term bf16 split), warp tile M16 x N8
        float aHH[4], aLH[4], aHL[4];
#pragma unroll
        for (int k = 0; k < 4; k++) { aHH[k] = 0.f; aLH[k] = 0.f; aHL[k] = 0.f; }

#pragma unroll
        for (int k16 = 0; k16 < 256; k16 += 16) {
            const uint32_t ko = (uint32_t)k16 * 2;
            uint32_t ah[4], al[4], bh[2], bl[2];
            LDSM4(ah, aBaseH + ko);
            LDSM4(al, aBaseL + ko);
            LDSM2(bh, bBaseH + ko);
            LDSM2(bl, bBaseL + ko);
            MMA16816(aHH, ah, bh);
            MMA16816(aLH, al, bh);
            MMA16816(aHL, ah, bl);
        }

        // ---- stage z to smem (sum split terms)
        {
            const int col = w * 8 + (lane & 3) * 2;
            const int row = lane >> 2;
            float z0 = aHH[0] + aLH[0] + aHL[0];
            float z1 = aHH[1] + aLH[1] + aHL[1];
            float z2 = aHH[2] + aLH[2] + aHL[2];
            float z3 = aHH[3] + aLH[3] + aHL[3];
            *(float2*)&zbuf[row * ZPAD + col] = make_float2(z0, z1);
            *(float2*)&zbuf[(row + 8) * ZPAD + col] = make_float2(z2, z3);
        }
        if (step + 1 < SS) { CP_WAIT1(); } else { CP_WAIT0(); }
        __syncthreads();

        // ---- gates, state update, publish h (coalesced: lanes span h-cols)
        {
            const int spos = dir ? (SS - 1 - step) : step;
            const int nxt = par ^ 1;
            float4 z4 = *(const float4*)&zbuf[fb * ZPAD + jl * 4];
            float zi = z4.x + sXZ[((par * 4 + 0) * 16 + fb) * XQ + jl];
            float zf = z4.y + sXZ[((par * 4 + 1) * 16 + fb) * XQ + jl];
            float zc = z4.z + sXZ[((par * 4 + 2) * 16 + fb) * XQ + jl];
            float zo = z4.w + sXZ[((par * 4 + 3) * 16 + fb) * XQ + jl];
            float ig = 1.f / (1.f + __expf(-zi));
            float fg = 1.f / (1.f + __expf(-zf));
            float og = 1.f / (1.f + __expf(-zo));
            float cc = fmaxf(zc, 0.f);
            cst = fg * cst + ig * cc;
            float h = og * fmaxf(cst, 0.f);
            __nv_bfloat16 hh = __float2bfloat16(h);
            __nv_bfloat16 hl = __float2bfloat16(h - __bfloat162float(hh));
            st16cg(&g_hxh[dir][bg][nxt][fb * HH + hc0 + jl], *(unsigned short*)&hh);
            st16cg(&g_hxl[dir][bg][nxt][fb * HH + hc0 + jl], *(unsigned short*)&hl);
            hist[((size_t)(bg * 16 + fb) * SS + spos) * HH + hc0 + jl] = h;
        }

        // ---- inter-CTA barrier (16 CTAs sharing (dir,bg)) — atomic counter (proven)
        __threadfence();
        __syncthreads();
        if (t == 0) {
            atomicAdd(&g_bar2[dir][bg], 1u);
            unsigned tgt = 16u * (unsigned)(step + 1);
            while (*((volatile unsigned*)&g_bar2[dir][bg]) < tgt) __nanosleep(20);
        }
        __syncthreads();
    }
#undef XZ_PREFETCH
}

// ---------------- phase 3: logits = (hf + hb).reshape(B,-1) @ Wd + bd ----------------
__global__ __launch_bounds__(256) void dense_out(
    const float* __restrict__ Wd, const float* __restrict__ bd, float* __restrict__ out)
{
    __shared__ float s0[256], s1[256];
    const int b = blockIdx.x, t = threadIdx.x;
    const float* hf = g_hf + (size_t)b * (SS * HH);
    const float* hb = g_hb + (size_t)b * (SS * HH);
    float a0 = 0.f, a1 = 0.f;
    for (int i = t * 4; i < SS * HH; i += 256 * 4) {
        float4 vf = *(const float4*)(hf + i);
        float4 vb = *(const float4*)(hb + i);
        float4 w0 = *(const float4*)(Wd + 2 * i);
        float4 w1 = *(const float4*)(Wd + 2 * i + 4);
        float v0 = vf.x + vb.x, v1 = vf.y + vb.y, v2 = vf.z + vb.z, v3 = vf.w + vb.w;
        a0 = fmaf(v0, w0.x, a0); a1 = fmaf(v0, w0.y, a1);
        a0 = fmaf(v1, w0.z, a0); a1 = fmaf(v1, w0.w, a1);
        a0 = fmaf(v2, w1.x, a0); a1 = fmaf(v2, w1.y, a1);
        a0 = fmaf(v3, w1.z, a0); a1 = fmaf(v3, w1.w, a1);
    }
    s0[t] = a0; s1[t] = a1;
    __syncthreads();
    for (int s = 128; s > 0; s >>= 1) {
        if (t < s) { s0[t] += s0[t + s]; s1[t] += s1[t + s]; }
        __syncthreads();
    }
    if (t == 0) {
        out[b * 2 + 0] = s0[0] + bd[0];
        out[b * 2 + 1] = s1[0] + bd[1];
    }
}

// ---------------- launcher ----------------
extern "C" void kernel_launch(void* const* d_in, const int* in_sizes, int n_in,
                              void* d_out, int out_size)
{
    const float* x  = (const float*)d_in[0];
    const float* kf = (const float*)d_in[1];
    const float* rf = (const float*)d_in[2];
    const float* bf = (const float*)d_in[3];
    const float* kb = (const float*)d_in[4];
    const float* rb = (const float*)d_in[5];
    const float* bbv= (const float*)d_in[6];
    const float* Wd = (const float*)d_in[7];
    const float* bd = (const float*)d_in[8];
    float* out = (float*)d_out;

    init_k<<<64, 256>>>();
    split_x<<<4096, 256>>>(x);
    split_wr<<<1280, 256>>>(kf, kb, rf, rb);

    cudaFuncSetAttribute(gemm_mma, cudaFuncAttributeMaxDynamicSharedMemorySize, GEMM_SMEM);
    gemm_mma<<<dim3(G4 / 128, MM / 128, 2), 256, GEMM_SMEM>>>(bf, bbv);

    cudaFuncSetAttribute(lstm_rec, cudaFuncAttributeMaxDynamicSharedMemorySize, LSTM_SMEM);
    lstm_rec<<<128, 256, LSTM_SMEM>>>();

    dense_out<<<BB, 256>>>(Wd, bd, out);
}